// round 15
// baseline (speedup 1.0000x reference)
#include <cuda_runtime.h>
#include <math.h>

#define B_   64
#define T_   256
#define W_   20
#define NP   6
#define NT   12
#define CC   32
#define FD   8
#define PR   64
#define NW   (B_*T_)      // 16384 windows
#define WB   8            // windows per chunk (4 pairs)
#define NCHUNK (NW / WB)  // 2048
#define GRIDA 304

typedef unsigned long long ull;

// scratch (static device arrays — no allocs)
__device__ float g_xg[NW * 4 * PR];   // precomputed input gates
__device__ float g_h [NW * PR];       // per-step hidden states
__device__ float g_prwT[72 * 64];     // projection weights, transposed (dup-written)
__device__ float g_WihT[64 * 256];    // Wih transposed [h][g]       (dup-written)

// ---------------------------------------------------------------------------
// fast math helpers
// ---------------------------------------------------------------------------
__device__ __forceinline__ ull fma2(ull a, ull b, ull c) {
    ull d;
    asm("fma.rn.f32x2 %0, %1, %2, %3;" : "=l"(d) : "l"(a), "l"(b), "l"(c));
    return d;
}
__device__ __forceinline__ float2 u2f2(ull v) {
    float2 r;
    asm("mov.b64 {%0, %1}, %2;" : "=f"(r.x), "=f"(r.y) : "l"(v));
    return r;
}
__device__ __forceinline__ ull pack2(float a, float b) {
    ull r;
    asm("mov.b64 %0, {%1, %2};" : "=l"(r) : "f"(a), "f"(b));
    return r;
}
__device__ __forceinline__ float tanha(float x) {
    float y;
    asm("tanh.approx.f32 %0, %1;" : "=f"(y) : "f"(x));
    return y;
}
__device__ __forceinline__ float siga(float x) {
    return fmaf(tanha(0.5f * x), 0.5f, 0.5f);
}

// ---------------------------------------------------------------------------
// smem layout (floats) — 28752 floats = 115008 B  (2 CTAs/SM: 230016 <= 233472)
// ---------------------------------------------------------------------------
#define OFF_W1P   0                    // [6ci][32o][4(k pad)] = 768
#define OFF_W1T   (OFF_W1P + 768)      // [12][32][4] = 1536
#define OFF_B1P   (OFF_W1T + 1536)     // 32
#define OFF_B1T   (OFF_B1P + 32)       // 32
#define OFF_W2P   (OFF_B1T + 32)       // [2enc][32ci][32o][4] = 8192
#define OFF_B2    (OFF_W2P + 8192)     // 64
#define OFF_FW    (OFF_B2  + 64)       // 8
#define OFF_FB    (OFF_FW  + 8)        // 8
#define OFF_XPI   (OFF_FB  + 8)        // [2buf][4p][6c][20w][2]  = 1920
#define OFF_XTI   (OFF_XPI + 1920)     // [2buf][4p][12c][20w][2] = 3840
#define OFF_H1I   (OFF_XTI + 3840)     // [4p][2enc][32c][20l][2] = 10240
#define OFF_CATI  (OFF_H1I + 10240)    // [2buf][4p][80j][2] = 1280
#define OFF_FEATI (OFF_CATI + 1280)    // [4p][64h][2] = 512
#define OFF_BSUM  (OFF_FEATI + 512)    // 256
#define OFF_PRB   (OFF_BSUM + 256)     // 64
#define SMEM_FLOATS (OFF_PRB + 64)     // 28752

// ---------------------------------------------------------------------------
// chunk input loader (transpose into window-pair layout)
// ---------------------------------------------------------------------------
__device__ __forceinline__ void load_chunk_inputs(
    float* s, const float* __restrict__ pressure, const float* __restrict__ torque,
    int kchunk, int buf, int t, int nthreads)
{
    const float* pg = pressure + (size_t)kchunk * WB * 120;
    for (int i = t; i < 960; i += nthreads) {
        int w8 = i / 120, r = i - w8 * 120, w = r / 6, c = r - w * 6;
        s[OFF_XPI + buf * 960 + (w8 >> 1) * 240 + (c * 20 + w) * 2 + (w8 & 1)] = pg[i];
    }
    const float* tg = torque + (size_t)kchunk * WB * 240;
    for (int i = t; i < 1920; i += nthreads) {
        int w8 = i / 240, r = i - w8 * 240, w = r / 12, c = r - w * 12;
        s[OFF_XTI + buf * 1920 + (w8 >> 1) * 480 + (c * 20 + w) * 2 + (w8 & 1)] = tg[i];
    }
}

// ---------------------------------------------------------------------------
// Kernel A: warp-specialized pipeline (R12 structure, init folded in)
//   warps 0-7 : conv1+conv2 for chunk k      (writes CAT[cur])
//   warps 8-15: load inputs k+1, frag k, projection+xg for chunk k-1
// ---------------------------------------------------------------------------
__global__ __launch_bounds__(512, 2) void encode_kernel(
    const float* __restrict__ pressure, const float* __restrict__ torque,
    const float* __restrict__ frag,
    const float* __restrict__ pw1, const float* __restrict__ pb1,
    const float* __restrict__ pw2, const float* __restrict__ pb2,
    const float* __restrict__ tw1, const float* __restrict__ tb1,
    const float* __restrict__ tw2, const float* __restrict__ tb2,
    const float* __restrict__ fw,  const float* __restrict__ fb,
    const float* __restrict__ prw, const float* __restrict__ prb,
    const float* __restrict__ Wih, const float* __restrict__ bih,
    const float* __restrict__ bhh)
{
    extern __shared__ __align__(16) float s[];
    const int tid = threadIdx.x;

    // ---- weight staging (smem) ----
    for (int i = tid; i < 576; i += 512) {              // pw1[o][ci][k]
        int o = i / 18, r = i - o * 18, ci = r / 3, k = r - ci * 3;
        s[OFF_W1P + (ci * 32 + o) * 4 + k] = pw1[i];
    }
    for (int i = tid; i < 1152; i += 512) {             // tw1[o][ci][k]
        int o = i / 36, r = i - o * 36, ci = r / 3, k = r - ci * 3;
        s[OFF_W1T + (ci * 32 + o) * 4 + k] = tw1[i];
    }
    for (int i = tid; i < 3072; i += 512) {             // pw2/tw2 [o][ci][k]
        int o = i / 96, r = i - o * 96, ci = r / 3, k = r - ci * 3;
        s[OFF_W2P +        (ci * 32 + o) * 4 + k] = pw2[i];
        s[OFF_W2P + 4096 + (ci * 32 + o) * 4 + k] = tw2[i];
    }
    for (int i = tid; i < 32; i += 512) {
        s[OFF_B1P + i] = pb1[i]; s[OFF_B1T + i] = tb1[i];
        s[OFF_B2  + i] = pb2[i]; s[OFF_B2 + 32 + i] = tb2[i];
    }
    if (tid < 8) { s[OFF_FW + tid] = fw[tid]; s[OFF_FB + tid] = fb[tid]; }
    // bias staging (smem)
    for (int i = tid; i < 256; i += 512) s[OFF_BSUM + i] = bih[i] + bhh[i];
    if (tid < 64) s[OFF_PRB + tid] = prb[tid];
    // duplicate global transposes (all CTAs write identical values; own writes
    // are ordered before reads by __syncthreads' CTA-scope memory barrier)
    for (int i = tid; i < 4608; i += 512) {             // prwT[j][o] = prw[o][j]
        int j = i >> 6, o = i & 63;
        g_prwT[i] = prw[o * 72 + j];
    }
    for (int i = tid; i < 16384; i += 512) {            // WihT[h][g] = Wih[g][h]
        int h = i >> 8, g = i & 255;
        g_WihT[i] = Wih[g * 64 + h];
    }
    __syncthreads();

    const int wid = tid >> 5, lane = tid & 31;
    const bool is_conv = wid < 8;
    const int p = wid & 3, enc = (wid >> 2) & 1;        // conv mapping
    const int ptid = tid - 256;                          // proj-group thread id

    const int kfirst = blockIdx.x;

    // prologue: all threads load inputs for first chunk into buf 0
    if (kfirst < NCHUNK)
        load_chunk_inputs(s, pressure, torque, kfirst, 0, tid, 512);
    __syncthreads();

    int cur = 0;
    for (int k = kfirst; k < NCHUNK + GRIDA; k += GRIDA, cur ^= 1) {
        const int prv = cur ^ 1;
        const bool conv_valid = (k < NCHUNK);

        if (is_conv) {
            if (conv_valid) {
                // ---- conv1 + relu (rolling-pair ull2 loads) ----
                {
                    const int o = lane;
                    ull acc[18];
                    if (enc == 0) {
                        ull bb = pack2(s[OFF_B1P + o], s[OFF_B1P + o]);
                        #pragma unroll
                        for (int l = 0; l < 18; l++) acc[l] = bb;
                        const float* xp = s + OFF_XPI + cur * 960 + p * 240;
                        #pragma unroll
                        for (int ci = 0; ci < 6; ci++) {
                            float4 w = *(const float4*)(s + OFF_W1P + (ci * 32 + o) * 4);
                            ull wx = pack2(w.x, w.x), wy = pack2(w.y, w.y), wz = pack2(w.z, w.z);
                            const ulonglong2* xr2 = (const ulonglong2*)(xp + ci * 40);
                            ulonglong2 pv = xr2[0];
                            ull p0 = pv.x, p1 = pv.y;
                            #pragma unroll
                            for (int l = 0; l < 18; l += 2) {
                                ulonglong2 nv = xr2[(l >> 1) + 1];
                                acc[l]   = fma2(wz, nv.x, fma2(wy, p1, fma2(wx, p0, acc[l])));
                                acc[l+1] = fma2(wz, nv.y, fma2(wy, nv.x, fma2(wx, p1, acc[l+1])));
                                p0 = nv.x; p1 = nv.y;
                            }
                        }
                    } else {
                        ull bb = pack2(s[OFF_B1T + o], s[OFF_B1T + o]);
                        #pragma unroll
                        for (int l = 0; l < 18; l++) acc[l] = bb;
                        const float* xp = s + OFF_XTI + cur * 1920 + p * 480;
                        #pragma unroll
                        for (int ci = 0; ci < 12; ci++) {
                            float4 w = *(const float4*)(s + OFF_W1T + (ci * 32 + o) * 4);
                            ull wx = pack2(w.x, w.x), wy = pack2(w.y, w.y), wz = pack2(w.z, w.z);
                            const ulonglong2* xr2 = (const ulonglong2*)(xp + ci * 40);
                            ulonglong2 pv = xr2[0];
                            ull p0 = pv.x, p1 = pv.y;
                            #pragma unroll
                            for (int l = 0; l < 18; l += 2) {
                                ulonglong2 nv = xr2[(l >> 1) + 1];
                                acc[l]   = fma2(wz, nv.x, fma2(wy, p1, fma2(wx, p0, acc[l])));
                                acc[l+1] = fma2(wz, nv.y, fma2(wy, nv.x, fma2(wx, p1, acc[l+1])));
                                p0 = nv.x; p1 = nv.y;
                            }
                        }
                    }
                    ulonglong2* hb2 = (ulonglong2*)(s + OFF_H1I + ((p * 2 + enc) * 32 + lane) * 40);
                    #pragma unroll
                    for (int l = 0; l < 18; l += 2) {
                        float2 v0 = u2f2(acc[l]), v1 = u2f2(acc[l + 1]);
                        ulonglong2 st;
                        st.x = pack2(fmaxf(v0.x, 0.f), fmaxf(v0.y, 0.f));
                        st.y = pack2(fmaxf(v1.x, 0.f), fmaxf(v1.y, 0.f));
                        hb2[l >> 1] = st;
                    }
                }
                __syncwarp();   // conv2 reads only this warp's conv1 output

                // ---- conv2 + relu + mean pool (rolling-pair ull2 loads) ----
                {
                    const int o = lane;
                    float bv = s[OFF_B2 + enc * 32 + o];
                    ull bb = pack2(bv, bv);
                    ull acc[16];
                    #pragma unroll
                    for (int l = 0; l < 16; l++) acc[l] = bb;
                    const float* hp = s + OFF_H1I + (p * 2 + enc) * 1280;
                    const float* wbase = s + OFF_W2P + enc * 4096;
                    #pragma unroll 4
                    for (int ci = 0; ci < 32; ci++) {
                        float4 w = *(const float4*)(wbase + (ci * 32 + o) * 4);
                        ull wx = pack2(w.x, w.x), wy = pack2(w.y, w.y), wz = pack2(w.z, w.z);
                        const ulonglong2* hr2 = (const ulonglong2*)(hp + ci * 40);
                        ulonglong2 pv = hr2[0];
                        ull p0 = pv.x, p1 = pv.y;
                        #pragma unroll
                        for (int l = 0; l < 16; l += 2) {
                            ulonglong2 nv = hr2[(l >> 1) + 1];
                            acc[l]   = fma2(wz, nv.x, fma2(wy, p1, fma2(wx, p0, acc[l])));
                            acc[l+1] = fma2(wz, nv.y, fma2(wy, nv.x, fma2(wx, p1, acc[l+1])));
                            p0 = nv.x; p1 = nv.y;
                        }
                    }
                    float s0 = 0.f, s1 = 0.f;
                    #pragma unroll
                    for (int l = 0; l < 16; l++) {
                        float2 v = u2f2(acc[l]);
                        s0 += fmaxf(v.x, 0.f); s1 += fmaxf(v.y, 0.f);
                    }
                    float2 pv; pv.x = s0 * (1.f / 16.f); pv.y = s1 * (1.f / 16.f);
                    ((float2*)(s + OFF_CATI))[cur * 320 + p * 80 + enc * 32 + o] = pv;
                }
            }
        } else {
            // ======== proj group (warps 8-15, 256 threads) ========
            if (conv_valid) {
                int knext = k + GRIDA;
                if (knext < NCHUNK)
                    load_chunk_inputs(s, pressure, torque, knext, prv, ptid, 256);
                if (ptid < 32) {    // fragility for chunk k -> CAT[cur]
                    int pp = ptid >> 3, kk = ptid & 7;
                    int b0 = k >> 5;   // (k*8)>>8
                    float v = fmaxf(frag[b0] * s[OFF_FW + kk] + s[OFF_FB + kk], 0.f);
                    float2 pv; pv.x = v; pv.y = v;
                    ((float2*)(s + OFF_CATI))[cur * 320 + pp * 80 + 64 + kk] = pv;
                }
            }
            if (k > kfirst) {
                const int kp = k - GRIDA;
                // ---- projection + relu (window-pair packed) ----
                {
                    const int pp = ptid >> 6, o = ptid & 63;
                    float pb = s[OFF_PRB + o];
                    ull acc = pack2(pb, pb);
                    const ull* cat = (const ull*)(s + OFF_CATI) + prv * 320 + pp * 80;
                    #pragma unroll
                    for (int j = 0; j < 72; j++) {
                        float w = g_prwT[j * 64 + o];
                        acc = fma2(pack2(w, w), cat[j], acc);
                    }
                    float2 v = u2f2(acc);
                    v.x = fmaxf(v.x, 0.f); v.y = fmaxf(v.y, 0.f);
                    ((float2*)(s + OFF_FEATI))[pp * 64 + o] = v;
                }
                asm volatile("bar.sync 2, 256;" ::: "memory");

                // ---- xg = feat @ Wih.T + bias (window-pair packed) ----
                {
                    const int pp = ptid >> 6, g0 = (ptid & 63) * 4;
                    ull a0 = pack2(s[OFF_BSUM + g0],     s[OFF_BSUM + g0]);
                    ull a1 = pack2(s[OFF_BSUM + g0 + 1], s[OFF_BSUM + g0 + 1]);
                    ull a2 = pack2(s[OFF_BSUM + g0 + 2], s[OFF_BSUM + g0 + 2]);
                    ull a3 = pack2(s[OFF_BSUM + g0 + 3], s[OFF_BSUM + g0 + 3]);
                    const ull* ft = (const ull*)(s + OFF_FEATI) + pp * 64;
                    #pragma unroll
                    for (int h = 0; h < 64; h++) {
                        float4 w = *(const float4*)(g_WihT + h * 256 + g0);
                        ull fp = ft[h];
                        a0 = fma2(pack2(w.x, w.x), fp, a0);
                        a1 = fma2(pack2(w.y, w.y), fp, a1);
                        a2 = fma2(pack2(w.z, w.z), fp, a2);
                        a3 = fma2(pack2(w.w, w.w), fp, a3);
                    }
                    float2 v0 = u2f2(a0), v1 = u2f2(a1), v2 = u2f2(a2), v3 = u2f2(a3);
                    const int win0 = kp * WB + pp * 2;
                    float4 o0; o0.x = v0.x; o0.y = v1.x; o0.z = v2.x; o0.w = v3.x;
                    float4 o1; o1.x = v0.y; o1.y = v1.y; o1.z = v2.y; o1.w = v3.y;
                    *(float4*)(g_xg + (size_t)win0 * 256 + g0)       = o0;
                    *(float4*)(g_xg + (size_t)(win0 + 1) * 256 + g0) = o1;
                }
            }
        }
        __syncthreads();
    }
}

// ---------------------------------------------------------------------------
// Kernel B: per-batch LSTM (j-mapped, 4 FFMA2 chains, 2 barriers)
// ---------------------------------------------------------------------------
__global__ __launch_bounds__(256) void lstm_kernel(
    const float* __restrict__ Whh, float* __restrict__ out)
{
    __shared__ __align__(16) float h_s[64];
    __shared__ float gates[256];

    const int b = blockIdx.x;
    const int j = threadIdx.x;

    ulonglong2 wv[16];
    const ulonglong2* wr = reinterpret_cast<const ulonglong2*>(Whh + j * 64);
    #pragma unroll
    for (int q = 0; q < 16; q++) wv[q] = wr[q];

    if (j < 64) h_s[j] = 0.f;
    float c = 0.f;

    const float* xg = g_xg + (size_t)b * T_ * 256;
    float xcur = xg[j];
    __syncthreads();

    for (int t = 0; t < T_; t++) {
        float xnext = (t + 1 < T_) ? xg[(size_t)(t + 1) * 256 + j] : 0.f;

        ull a0 = 0ull, a1 = 0ull, a2 = 0ull, a3 = 0ull;
        const ulonglong2* h2 = reinterpret_cast<const ulonglong2*>(h_s);
        #pragma unroll
        for (int q = 0; q < 8; q++) {
            ulonglong2 h0 = h2[2 * q], h1 = h2[2 * q + 1];
            a0 = fma2(wv[2 * q].x,     h0.x, a0);
            a1 = fma2(wv[2 * q].y,     h0.y, a1);
            a2 = fma2(wv[2 * q + 1].x, h1.x, a2);
            a3 = fma2(wv[2 * q + 1].y, h1.y, a3);
        }
        float2 p0 = u2f2(a0), p1 = u2f2(a1), p2 = u2f2(a2), p3 = u2f2(a3);
        gates[j] = xcur + ((p0.x + p0.y) + (p1.x + p1.y))
                        + ((p2.x + p2.y) + (p3.x + p3.y));
        xcur = xnext;
        __syncthreads();

        if (j < 64) {
            float gi = gates[j],       gf = gates[64 + j];
            float gg = gates[128 + j], go = gates[192 + j];
            c = siga(gf) * c + siga(gi) * tanha(gg);
            float h = siga(go) * tanha(c);
            h_s[j] = h;
            g_h[((size_t)b * T_ + t) * 64 + j] = h;
        }
        __syncthreads();
    }

    if (j < 64) {
        out[(size_t)B_ * T_ * 4 + b * 64 + j] = h_s[j];                 // hT
        out[(size_t)B_ * T_ * 4 + B_ * 64 + b * 64 + j] = c;            // cT
    }
}

// ---------------------------------------------------------------------------
// Kernel C: head
// ---------------------------------------------------------------------------
__global__ __launch_bounds__(128) void head_kernel(
    const float* __restrict__ hw, const float* __restrict__ hb,
    float* __restrict__ out)
{
    __shared__ float s_hw[256];
    __shared__ float s_hb[4];
    const int tid = threadIdx.x;
    s_hw[tid] = hw[tid];
    s_hw[tid + 128] = hw[tid + 128];
    if (tid < 4) s_hb[tid] = hb[tid];
    __syncthreads();

    const int bt = blockIdx.x * 128 + tid;   // grid 128 x 128 = 16384
    const float4* h4 = reinterpret_cast<const float4*>(g_h + (size_t)bt * 64);
    float a0 = s_hb[0], a1 = s_hb[1], a2 = s_hb[2], a3 = s_hb[3];
    #pragma unroll
    for (int q = 0; q < 16; q++) {
        float4 hv = h4[q];
        a0 += s_hw[      q*4]*hv.x + s_hw[      q*4+1]*hv.y + s_hw[      q*4+2]*hv.z + s_hw[      q*4+3]*hv.w;
        a1 += s_hw[ 64 + q*4]*hv.x + s_hw[ 64 + q*4+1]*hv.y + s_hw[ 64 + q*4+2]*hv.z + s_hw[ 64 + q*4+3]*hv.w;
        a2 += s_hw[128 + q*4]*hv.x + s_hw[128 + q*4+1]*hv.y + s_hw[128 + q*4+2]*hv.z + s_hw[128 + q*4+3]*hv.w;
        a3 += s_hw[192 + q*4]*hv.x + s_hw[192 + q*4+1]*hv.y + s_hw[192 + q*4+2]*hv.z + s_hw[192 + q*4+3]*hv.w;
    }
    float4 r;
    r.x = siga(a0); r.y = siga(a1); r.z = siga(a2); r.w = siga(a3);
    *reinterpret_cast<float4*>(out + (size_t)bt * 4) = r;
}

// ---------------------------------------------------------------------------
extern "C" void kernel_launch(void* const* d_in, const int* in_sizes, int n_in,
                              void* d_out, int out_size)
{
    const float* pressure = (const float*)d_in[0];
    const float* torque   = (const float*)d_in[1];
    const float* frag     = (const float*)d_in[2];
    const float* pw1 = (const float*)d_in[3];
    const float* pb1 = (const float*)d_in[4];
    const float* pw2 = (const float*)d_in[5];
    const float* pb2 = (const float*)d_in[6];
    const float* tw1 = (const float*)d_in[7];
    const float* tb1 = (const float*)d_in[8];
    const float* tw2 = (const float*)d_in[9];
    const float* tb2 = (const float*)d_in[10];
    const float* fw  = (const float*)d_in[11];
    const float* fb  = (const float*)d_in[12];
    const float* prw = (const float*)d_in[13];
    const float* prb = (const float*)d_in[14];
    const float* Wih = (const float*)d_in[15];
    const float* Whh = (const float*)d_in[16];
    const float* bih = (const float*)d_in[17];
    const float* bhh = (const float*)d_in[18];
    const float* hw  = (const float*)d_in[19];
    const float* hb  = (const float*)d_in[20];

    const int smem_bytes = SMEM_FLOATS * sizeof(float);   // 115008 B
    cudaFuncSetAttribute(encode_kernel,
                         cudaFuncAttributeMaxDynamicSharedMemorySize, smem_bytes);

    encode_kernel<<<GRIDA, 512, smem_bytes>>>(
        pressure, torque, frag,
        pw1, pb1, pw2, pb2, tw1, tb1, tw2, tb2,
        fw, fb, prw, prb, Wih, bih, bhh);
    lstm_kernel<<<B_, 256>>>(Whh, (float*)d_out);
    head_kernel<<<128, 128>>>(hw, hb, (float*)d_out);
}

// round 17
// speedup vs baseline: 1.1292x; 1.1292x over previous
#include <cuda_runtime.h>
#include <math.h>

#define B_   64
#define T_   256
#define W_   20
#define NP   6
#define NT   12
#define CC   32
#define FD   8
#define PR   64
#define NW   (B_*T_)      // 16384 windows
#define WB   8            // windows per chunk (4 pairs)
#define NCHUNK (NW / WB)  // 2048
#define GRIDA 304

typedef unsigned long long ull;

// scratch (static device arrays — no allocs)
__device__ float g_xg[NW * 4 * PR];   // precomputed input gates
__device__ float g_h [NW * PR];       // per-step hidden states
__device__ float g_prwT[72 * 64];     // projection weights, transposed
__device__ float g_WihT[64 * 256];    // Wih transposed [h][g]
__device__ float g_bsum[256];         // bih + bhh

// ---------------------------------------------------------------------------
// fast math helpers
// ---------------------------------------------------------------------------
__device__ __forceinline__ ull fma2(ull a, ull b, ull c) {
    ull d;
    asm("fma.rn.f32x2 %0, %1, %2, %3;" : "=l"(d) : "l"(a), "l"(b), "l"(c));
    return d;
}
__device__ __forceinline__ float2 u2f2(ull v) {
    float2 r;
    asm("mov.b64 {%0, %1}, %2;" : "=f"(r.x), "=f"(r.y) : "l"(v));
    return r;
}
__device__ __forceinline__ ull pack2(float a, float b) {
    ull r;
    asm("mov.b64 %0, {%1, %2};" : "=l"(r) : "f"(a), "f"(b));
    return r;
}
__device__ __forceinline__ float tanha(float x) {
    float y;
    asm("tanh.approx.f32 %0, %1;" : "=f"(y) : "f"(x));
    return y;
}
__device__ __forceinline__ float siga(float x) {
    return fmaf(tanha(0.5f * x), 0.5f, 0.5f);
}

// ---------------------------------------------------------------------------
// smem layout (floats) — 28432 floats = 113728 B  (2 CTAs/SM)
// ---------------------------------------------------------------------------
#define OFF_W1P   0                    // [6ci][32o][4(k pad)] = 768
#define OFF_W1T   (OFF_W1P + 768)      // [12][32][4] = 1536
#define OFF_B1P   (OFF_W1T + 1536)     // 32
#define OFF_B1T   (OFF_B1P + 32)       // 32
#define OFF_W2P   (OFF_B1T + 32)       // [2enc][32ci][32o][4] = 8192
#define OFF_B2    (OFF_W2P + 8192)     // 64
#define OFF_FW    (OFF_B2  + 64)       // 8
#define OFF_FB    (OFF_FW  + 8)        // 8
#define OFF_XPI   (OFF_FB  + 8)        // [2buf][4p][6c][20w][2]  = 1920
#define OFF_XTI   (OFF_XPI + 1920)     // [2buf][4p][12c][20w][2] = 3840
#define OFF_H1I   (OFF_XTI + 3840)     // [4p][2enc][32c][20l][2] = 10240
#define OFF_CATI  (OFF_H1I + 10240)    // [2buf][4p][80j][2] = 1280
#define OFF_FEATI (OFF_CATI + 1280)    // [4p][64h][2] = 512
#define SMEM_FLOATS (OFF_FEATI + 512)  // 28432

// ---------------------------------------------------------------------------
// Kernel 0: weight transposes
// ---------------------------------------------------------------------------
__global__ __launch_bounds__(256) void init_kernel(
    const float* __restrict__ prw, const float* __restrict__ Wih,
    const float* __restrict__ bih, const float* __restrict__ bhh)
{
    int i = blockIdx.x * 256 + threadIdx.x;
    if (i < 4608) { int j = i >> 6, o = i & 63; g_prwT[i] = prw[o * 72 + j]; }
    if (i < 16384) { int h = i >> 8, g = i & 255; g_WihT[i] = Wih[g * 64 + h]; }
    if (i < 256) g_bsum[i] = bih[i] + bhh[i];
}

// ---------------------------------------------------------------------------
// chunk input loader (transpose into window-pair layout)
// ---------------------------------------------------------------------------
__device__ __forceinline__ void load_chunk_inputs(
    float* s, const float* __restrict__ pressure, const float* __restrict__ torque,
    int kchunk, int buf, int t, int nthreads)
{
    const float* pg = pressure + (size_t)kchunk * WB * 120;
    for (int i = t; i < 960; i += nthreads) {
        int w8 = i / 120, r = i - w8 * 120, w = r / 6, c = r - w * 6;
        s[OFF_XPI + buf * 960 + (w8 >> 1) * 240 + (c * 20 + w) * 2 + (w8 & 1)] = pg[i];
    }
    const float* tg = torque + (size_t)kchunk * WB * 240;
    for (int i = t; i < 1920; i += nthreads) {
        int w8 = i / 240, r = i - w8 * 240, w = r / 12, c = r - w * 12;
        s[OFF_XTI + buf * 1920 + (w8 >> 1) * 480 + (c * 20 + w) * 2 + (w8 & 1)] = tg[i];
    }
}

// ---------------------------------------------------------------------------
// Kernel A: warp-specialized pipeline
//   warps 0-7 : conv1+conv2 for chunk k      (writes CAT[cur])
//   warps 8-15: load inputs k+1, frag k, projection+xg for chunk k-1
// stage 5 uses 128 threads x 2 pairs: halves Wih L1tex traffic
// ---------------------------------------------------------------------------
__global__ __launch_bounds__(512, 2) void encode_kernel(
    const float* __restrict__ pressure, const float* __restrict__ torque,
    const float* __restrict__ frag,
    const float* __restrict__ pw1, const float* __restrict__ pb1,
    const float* __restrict__ pw2, const float* __restrict__ pb2,
    const float* __restrict__ tw1, const float* __restrict__ tb1,
    const float* __restrict__ tw2, const float* __restrict__ tb2,
    const float* __restrict__ fw,  const float* __restrict__ fb,
    const float* __restrict__ prb)
{
    extern __shared__ __align__(16) float s[];
    const int tid = threadIdx.x;

    // ---- weight staging ----
    for (int i = tid; i < 576; i += 512) {              // pw1[o][ci][k]
        int o = i / 18, r = i - o * 18, ci = r / 3, k = r - ci * 3;
        s[OFF_W1P + (ci * 32 + o) * 4 + k] = pw1[i];
    }
    for (int i = tid; i < 1152; i += 512) {             // tw1[o][ci][k]
        int o = i / 36, r = i - o * 36, ci = r / 3, k = r - ci * 3;
        s[OFF_W1T + (ci * 32 + o) * 4 + k] = tw1[i];
    }
    for (int i = tid; i < 3072; i += 512) {             // pw2/tw2 [o][ci][k]
        int o = i / 96, r = i - o * 96, ci = r / 3, k = r - ci * 3;
        s[OFF_W2P +        (ci * 32 + o) * 4 + k] = pw2[i];
        s[OFF_W2P + 4096 + (ci * 32 + o) * 4 + k] = tw2[i];
    }
    for (int i = tid; i < 32; i += 512) {
        s[OFF_B1P + i] = pb1[i]; s[OFF_B1T + i] = tb1[i];
        s[OFF_B2  + i] = pb2[i]; s[OFF_B2 + 32 + i] = tb2[i];
    }
    if (tid < 8) { s[OFF_FW + tid] = fw[tid]; s[OFF_FB + tid] = fb[tid]; }
    __syncthreads();

    const int wid = tid >> 5, lane = tid & 31;
    const bool is_conv = wid < 8;
    const int p = wid & 3, enc = (wid >> 2) & 1;        // conv mapping
    const int ptid = tid - 256;                          // proj-group thread id

    const int kfirst = blockIdx.x;

    // prologue: all threads load inputs for first chunk into buf 0
    if (kfirst < NCHUNK)
        load_chunk_inputs(s, pressure, torque, kfirst, 0, tid, 512);
    __syncthreads();

    int cur = 0;
    for (int k = kfirst; k < NCHUNK + GRIDA; k += GRIDA, cur ^= 1) {
        const int prv = cur ^ 1;
        const bool conv_valid = (k < NCHUNK);

        if (is_conv) {
            if (conv_valid) {
                // ---- conv1 + relu (rolling-pair ull2 loads) ----
                {
                    const int o = lane;
                    ull acc[18];
                    if (enc == 0) {
                        ull bb = pack2(s[OFF_B1P + o], s[OFF_B1P + o]);
                        #pragma unroll
                        for (int l = 0; l < 18; l++) acc[l] = bb;
                        const float* xp = s + OFF_XPI + cur * 960 + p * 240;
                        #pragma unroll
                        for (int ci = 0; ci < 6; ci++) {
                            float4 w = *(const float4*)(s + OFF_W1P + (ci * 32 + o) * 4);
                            ull wx = pack2(w.x, w.x), wy = pack2(w.y, w.y), wz = pack2(w.z, w.z);
                            const ulonglong2* xr2 = (const ulonglong2*)(xp + ci * 40);
                            ulonglong2 pv = xr2[0];
                            ull p0 = pv.x, p1 = pv.y;
                            #pragma unroll
                            for (int l = 0; l < 18; l += 2) {
                                ulonglong2 nv = xr2[(l >> 1) + 1];
                                acc[l]   = fma2(wz, nv.x, fma2(wy, p1, fma2(wx, p0, acc[l])));
                                acc[l+1] = fma2(wz, nv.y, fma2(wy, nv.x, fma2(wx, p1, acc[l+1])));
                                p0 = nv.x; p1 = nv.y;
                            }
                        }
                    } else {
                        ull bb = pack2(s[OFF_B1T + o], s[OFF_B1T + o]);
                        #pragma unroll
                        for (int l = 0; l < 18; l++) acc[l] = bb;
                        const float* xp = s + OFF_XTI + cur * 1920 + p * 480;
                        #pragma unroll
                        for (int ci = 0; ci < 12; ci++) {
                            float4 w = *(const float4*)(s + OFF_W1T + (ci * 32 + o) * 4);
                            ull wx = pack2(w.x, w.x), wy = pack2(w.y, w.y), wz = pack2(w.z, w.z);
                            const ulonglong2* xr2 = (const ulonglong2*)(xp + ci * 40);
                            ulonglong2 pv = xr2[0];
                            ull p0 = pv.x, p1 = pv.y;
                            #pragma unroll
                            for (int l = 0; l < 18; l += 2) {
                                ulonglong2 nv = xr2[(l >> 1) + 1];
                                acc[l]   = fma2(wz, nv.x, fma2(wy, p1, fma2(wx, p0, acc[l])));
                                acc[l+1] = fma2(wz, nv.y, fma2(wy, nv.x, fma2(wx, p1, acc[l+1])));
                                p0 = nv.x; p1 = nv.y;
                            }
                        }
                    }
                    ulonglong2* hb2 = (ulonglong2*)(s + OFF_H1I + ((p * 2 + enc) * 32 + lane) * 40);
                    #pragma unroll
                    for (int l = 0; l < 18; l += 2) {
                        float2 v0 = u2f2(acc[l]), v1 = u2f2(acc[l + 1]);
                        ulonglong2 st;
                        st.x = pack2(fmaxf(v0.x, 0.f), fmaxf(v0.y, 0.f));
                        st.y = pack2(fmaxf(v1.x, 0.f), fmaxf(v1.y, 0.f));
                        hb2[l >> 1] = st;
                    }
                }
                __syncwarp();   // conv2 reads only this warp's conv1 output

                // ---- conv2 + relu + mean pool (rolling-pair ull2 loads) ----
                {
                    const int o = lane;
                    float bv = s[OFF_B2 + enc * 32 + o];
                    ull bb = pack2(bv, bv);
                    ull acc[16];
                    #pragma unroll
                    for (int l = 0; l < 16; l++) acc[l] = bb;
                    const float* hp = s + OFF_H1I + (p * 2 + enc) * 1280;
                    const float* wbase = s + OFF_W2P + enc * 4096;
                    #pragma unroll 4
                    for (int ci = 0; ci < 32; ci++) {
                        float4 w = *(const float4*)(wbase + (ci * 32 + o) * 4);
                        ull wx = pack2(w.x, w.x), wy = pack2(w.y, w.y), wz = pack2(w.z, w.z);
                        const ulonglong2* hr2 = (const ulonglong2*)(hp + ci * 40);
                        ulonglong2 pv = hr2[0];
                        ull p0 = pv.x, p1 = pv.y;
                        #pragma unroll
                        for (int l = 0; l < 16; l += 2) {
                            ulonglong2 nv = hr2[(l >> 1) + 1];
                            acc[l]   = fma2(wz, nv.x, fma2(wy, p1, fma2(wx, p0, acc[l])));
                            acc[l+1] = fma2(wz, nv.y, fma2(wy, nv.x, fma2(wx, p1, acc[l+1])));
                            p0 = nv.x; p1 = nv.y;
                        }
                    }
                    float s0 = 0.f, s1 = 0.f;
                    #pragma unroll
                    for (int l = 0; l < 16; l++) {
                        float2 v = u2f2(acc[l]);
                        s0 += fmaxf(v.x, 0.f); s1 += fmaxf(v.y, 0.f);
                    }
                    float2 pv; pv.x = s0 * (1.f / 16.f); pv.y = s1 * (1.f / 16.f);
                    ((float2*)(s + OFF_CATI))[cur * 320 + p * 80 + enc * 32 + o] = pv;
                }
            }
        } else {
            // ======== proj group (warps 8-15, 256 threads) ========
            if (conv_valid) {
                int knext = k + GRIDA;
                if (knext < NCHUNK)
                    load_chunk_inputs(s, pressure, torque, knext, prv, ptid, 256);
                if (ptid < 32) {    // fragility for chunk k -> CAT[cur]
                    int pp = ptid >> 3, kk = ptid & 7;
                    int b0 = k >> 5;   // (k*8)>>8
                    float v = fmaxf(frag[b0] * s[OFF_FW + kk] + s[OFF_FB + kk], 0.f);
                    float2 pv; pv.x = v; pv.y = v;
                    ((float2*)(s + OFF_CATI))[cur * 320 + pp * 80 + 64 + kk] = pv;
                }
            }
            if (k > kfirst) {
                const int kp = k - GRIDA;
                // ---- projection + relu (window-pair packed, 256 threads) ----
                {
                    const int pp = ptid >> 6, o = ptid & 63;
                    float pb = __ldg(prb + o);
                    ull acc = pack2(pb, pb);
                    const ull* cat = (const ull*)(s + OFF_CATI) + prv * 320 + pp * 80;
                    #pragma unroll
                    for (int j = 0; j < 72; j++) {
                        float w = __ldg(g_prwT + j * 64 + o);
                        acc = fma2(pack2(w, w), cat[j], acc);
                    }
                    float2 v = u2f2(acc);
                    v.x = fmaxf(v.x, 0.f); v.y = fmaxf(v.y, 0.f);
                    ((float2*)(s + OFF_FEATI))[pp * 64 + o] = v;
                }
                asm volatile("bar.sync 2, 256;" ::: "memory");

                // ---- xg: 128 threads x 2 pairs (Wih loaded once per 2 pairs) ----
                if (ptid < 128) {
                    const int half = ptid >> 6;          // 0: pairs 0,1 | 1: pairs 2,3
                    const int g0 = (ptid & 63) * 4;
                    ull a[2][4];
                    #pragma unroll
                    for (int i = 0; i < 4; i++) {
                        float bv = g_bsum[g0 + i];
                        ull bp = pack2(bv, bv);
                        a[0][i] = bp; a[1][i] = bp;
                    }
                    const ull* ft0 = (const ull*)(s + OFF_FEATI) + (half * 2) * 64;
                    const ull* ft1 = ft0 + 64;
                    #pragma unroll 8
                    for (int h = 0; h < 64; h++) {
                        float4 w = __ldg((const float4*)(g_WihT + h * 256 + g0));
                        ull wd0 = pack2(w.x, w.x), wd1 = pack2(w.y, w.y);
                        ull wd2 = pack2(w.z, w.z), wd3 = pack2(w.w, w.w);
                        ull f0 = ft0[h], f1 = ft1[h];
                        a[0][0] = fma2(wd0, f0, a[0][0]);
                        a[0][1] = fma2(wd1, f0, a[0][1]);
                        a[0][2] = fma2(wd2, f0, a[0][2]);
                        a[0][3] = fma2(wd3, f0, a[0][3]);
                        a[1][0] = fma2(wd0, f1, a[1][0]);
                        a[1][1] = fma2(wd1, f1, a[1][1]);
                        a[1][2] = fma2(wd2, f1, a[1][2]);
                        a[1][3] = fma2(wd3, f1, a[1][3]);
                    }
                    #pragma unroll
                    for (int q = 0; q < 2; q++) {
                        const int pp = half * 2 + q;
                        const int win0 = kp * WB + pp * 2;
                        float2 v0 = u2f2(a[q][0]), v1 = u2f2(a[q][1]);
                        float2 v2 = u2f2(a[q][2]), v3 = u2f2(a[q][3]);
                        float4 lo; lo.x = v0.x; lo.y = v1.x; lo.z = v2.x; lo.w = v3.x;
                        float4 hi; hi.x = v0.y; hi.y = v1.y; hi.z = v2.y; hi.w = v3.y;
                        *(float4*)(g_xg + (size_t)win0 * 256 + g0)       = lo;
                        *(float4*)(g_xg + (size_t)(win0 + 1) * 256 + g0) = hi;
                    }
                }
            }
        }
        __syncthreads();
    }
}

// ---------------------------------------------------------------------------
// Kernel B: per-batch LSTM (j-mapped, 4 FFMA2 chains, 2 barriers)
// ---------------------------------------------------------------------------
__global__ __launch_bounds__(256) void lstm_kernel(
    const float* __restrict__ Whh, float* __restrict__ out)
{
    __shared__ __align__(16) float h_s[64];
    __shared__ float gates[256];

    const int b = blockIdx.x;
    const int j = threadIdx.x;

    ulonglong2 wv[16];
    const ulonglong2* wr = reinterpret_cast<const ulonglong2*>(Whh + j * 64);
    #pragma unroll
    for (int q = 0; q < 16; q++) wv[q] = wr[q];

    if (j < 64) h_s[j] = 0.f;
    float c = 0.f;

    const float* xg = g_xg + (size_t)b * T_ * 256;
    float xcur = xg[j];
    __syncthreads();

    for (int t = 0; t < T_; t++) {
        float xnext = (t + 1 < T_) ? xg[(size_t)(t + 1) * 256 + j] : 0.f;

        ull a0 = 0ull, a1 = 0ull, a2 = 0ull, a3 = 0ull;
        const ulonglong2* h2 = reinterpret_cast<const ulonglong2*>(h_s);
        #pragma unroll
        for (int q = 0; q < 8; q++) {
            ulonglong2 h0 = h2[2 * q], h1 = h2[2 * q + 1];
            a0 = fma2(wv[2 * q].x,     h0.x, a0);
            a1 = fma2(wv[2 * q].y,     h0.y, a1);
            a2 = fma2(wv[2 * q + 1].x, h1.x, a2);
            a3 = fma2(wv[2 * q + 1].y, h1.y, a3);
        }
        float2 p0 = u2f2(a0), p1 = u2f2(a1), p2 = u2f2(a2), p3 = u2f2(a3);
        gates[j] = xcur + ((p0.x + p0.y) + (p1.x + p1.y))
                        + ((p2.x + p2.y) + (p3.x + p3.y));
        xcur = xnext;
        __syncthreads();

        if (j < 64) {
            float gi = gates[j],       gf = gates[64 + j];
            float gg = gates[128 + j], go = gates[192 + j];
            c = siga(gf) * c + siga(gi) * tanha(gg);
            float h = siga(go) * tanha(c);
            h_s[j] = h;
            g_h[((size_t)b * T_ + t) * 64 + j] = h;
        }
        __syncthreads();
    }

    if (j < 64) {
        out[(size_t)B_ * T_ * 4 + b * 64 + j] = h_s[j];                 // hT
        out[(size_t)B_ * T_ * 4 + B_ * 64 + b * 64 + j] = c;            // cT
    }
}

// ---------------------------------------------------------------------------
// Kernel C: head
// ---------------------------------------------------------------------------
__global__ __launch_bounds__(128) void head_kernel(
    const float* __restrict__ hw, const float* __restrict__ hb,
    float* __restrict__ out)
{
    __shared__ float s_hw[256];
    __shared__ float s_hb[4];
    const int tid = threadIdx.x;
    s_hw[tid] = hw[tid];
    s_hw[tid + 128] = hw[tid + 128];
    if (tid < 4) s_hb[tid] = hb[tid];
    __syncthreads();

    const int bt = blockIdx.x * 128 + tid;   // grid 128 x 128 = 16384
    const float4* h4 = reinterpret_cast<const float4*>(g_h + (size_t)bt * 64);
    float a0 = s_hb[0], a1 = s_hb[1], a2 = s_hb[2], a3 = s_hb[3];
    #pragma unroll
    for (int q = 0; q < 16; q++) {
        float4 hv = h4[q];
        a0 += s_hw[      q*4]*hv.x + s_hw[      q*4+1]*hv.y + s_hw[      q*4+2]*hv.z + s_hw[      q*4+3]*hv.w;
        a1 += s_hw[ 64 + q*4]*hv.x + s_hw[ 64 + q*4+1]*hv.y + s_hw[ 64 + q*4+2]*hv.z + s_hw[ 64 + q*4+3]*hv.w;
        a2 += s_hw[128 + q*4]*hv.x + s_hw[128 + q*4+1]*hv.y + s_hw[128 + q*4+2]*hv.z + s_hw[128 + q*4+3]*hv.w;
        a3 += s_hw[192 + q*4]*hv.x + s_hw[192 + q*4+1]*hv.y + s_hw[192 + q*4+2]*hv.z + s_hw[192 + q*4+3]*hv.w;
    }
    float4 r;
    r.x = siga(a0); r.y = siga(a1); r.z = siga(a2); r.w = siga(a3);
    *reinterpret_cast<float4*>(out + (size_t)bt * 4) = r;
}

// ---------------------------------------------------------------------------
extern "C" void kernel_launch(void* const* d_in, const int* in_sizes, int n_in,
                              void* d_out, int out_size)
{
    const float* pressure = (const float*)d_in[0];
    const float* torque   = (const float*)d_in[1];
    const float* frag     = (const float*)d_in[2];
    const float* pw1 = (const float*)d_in[3];
    const float* pb1 = (const float*)d_in[4];
    const float* pw2 = (const float*)d_in[5];
    const float* pb2 = (const float*)d_in[6];
    const float* tw1 = (const float*)d_in[7];
    const float* tb1 = (const float*)d_in[8];
    const float* tw2 = (const float*)d_in[9];
    const float* tb2 = (const float*)d_in[10];
    const float* fw  = (const float*)d_in[11];
    const float* fb  = (const float*)d_in[12];
    const float* prw = (const float*)d_in[13];
    const float* prb = (const float*)d_in[14];
    const float* Wih = (const float*)d_in[15];
    const float* Whh = (const float*)d_in[16];
    const float* bih = (const float*)d_in[17];
    const float* bhh = (const float*)d_in[18];
    const float* hw  = (const float*)d_in[19];
    const float* hb  = (const float*)d_in[20];

    const int smem_bytes = SMEM_FLOATS * sizeof(float);   // 113728 B
    cudaFuncSetAttribute(encode_kernel,
                         cudaFuncAttributeMaxDynamicSharedMemorySize, smem_bytes);

    init_kernel<<<64, 256>>>(prw, Wih, bih, bhh);
    encode_kernel<<<GRIDA, 512, smem_bytes>>>(
        pressure, torque, frag,
        pw1, pb1, pw2, pb2, tw1, tb1, tw2, tb2,
        fw, fb, prb);
    lstm_kernel<<<B_, 256>>>(Whh, (float*)d_out);
    head_kernel<<<128, 128>>>(hw, hb, (float*)d_out);
}